// round 6
// baseline (speedup 1.0000x reference)
#include <cuda_runtime.h>
#include <cuda_fp16.h>
#include <cstdint>

#define BATCH   16384
#define HID     512
#define NLAYERS 8
#define NOUT    16
#define WSCALE  4.4194173824159215e-04f  /* 0.01 / sqrt(512) */
#define BSCALE  0.01f
#define SLOPE   0.2f
#define GAIN    1.41421356237f
#define EPSV    1e-8f

// ---------------------------------------------------------------------------
// Scratch (allocation-free rule: __device__ globals)
// ---------------------------------------------------------------------------
__device__ __half g_Ahi[2][(size_t)BATCH * HID];
__device__ __half g_Alo[2][(size_t)BATCH * HID];
__device__ __half g_Whi[(size_t)NLAYERS * HID * HID];
__device__ __half g_Wlo[(size_t)NLAYERS * HID * HID];

// ---------------------------------------------------------------------------
// Helpers
// ---------------------------------------------------------------------------
__device__ __forceinline__ uint32_t smem_u32(const void* p) {
    uint32_t a;
    asm("{ .reg .u64 t; cvta.to.shared.u64 t, %1; cvt.u32.u64 %0, t; }"
        : "=r"(a) : "l"(p));
    return a;
}
__device__ __forceinline__ void ldm_x4(uint32_t addr, uint32_t r[4]) {
    asm volatile(
        "ldmatrix.sync.aligned.m8n8.x4.shared.b16 {%0,%1,%2,%3}, [%4];"
        : "=r"(r[0]), "=r"(r[1]), "=r"(r[2]), "=r"(r[3]) : "r"(addr));
}
__device__ __forceinline__ void mma16816(float c[4], const uint32_t a[4],
                                         const uint32_t b[2]) {
    asm volatile(
        "mma.sync.aligned.m16n8k16.row.col.f32.f16.f16.f32 "
        "{%0,%1,%2,%3}, {%4,%5,%6,%7}, {%8,%9}, {%0,%1,%2,%3};"
        : "+f"(c[0]), "+f"(c[1]), "+f"(c[2]), "+f"(c[3])
        : "r"(a[0]), "r"(a[1]), "r"(a[2]), "r"(a[3]), "r"(b[0]), "r"(b[1]));
}
#define CP_ASYNC16(sa, ga) \
    asm volatile("cp.async.cg.shared.global [%0], [%1], 16;" :: "r"(sa), "l"(ga))
#define CP_COMMIT() asm volatile("cp.async.commit_group;")
#define CP_WAIT2() asm volatile("cp.async.wait_group 2;")
#define CP_WAIT1() asm volatile("cp.async.wait_group 1;")
#define CP_WAIT0() asm volatile("cp.async.wait_group 0;")

// ---------------------------------------------------------------------------
// Weight conversion: w_eff = w * WSCALE, split fp16 hi + lo
// ---------------------------------------------------------------------------
__global__ void wconv_kernel(const float* __restrict__ w,
                             __half* __restrict__ whi,
                             __half* __restrict__ wlo) {
    size_t i = (size_t)blockIdx.x * blockDim.x + threadIdx.x;
    float4 v = ((const float4*)w)[i];
    float e[4] = {v.x * WSCALE, v.y * WSCALE, v.z * WSCALE, v.w * WSCALE};
    union { uint2 u; __half h[4]; } ph, pl;
#pragma unroll
    for (int j = 0; j < 4; j++) {
        __half hh = __float2half_rn(e[j]);
        ph.h[j] = hh;
        pl.h[j] = __float2half_rn(e[j] - __half2float(hh));
    }
    ((uint2*)whi)[i] = ph.u;
    ((uint2*)wlo)[i] = pl.u;
}

// ---------------------------------------------------------------------------
// Pixel norm + fp16 hi/lo split
// ---------------------------------------------------------------------------
__global__ void pixelnorm_split_kernel(const float* __restrict__ z,
                                       __half* __restrict__ ahi,
                                       __half* __restrict__ alo) {
    const int row = blockIdx.x;
    const int tid = threadIdx.x;
    float4 v = ((const float4*)(z + (size_t)row * HID))[tid];
    float s = v.x * v.x + v.y * v.y + v.z * v.z + v.w * v.w;
#pragma unroll
    for (int o = 16; o > 0; o >>= 1) s += __shfl_xor_sync(0xffffffffu, s, o);
    __shared__ float ws[4];
    if ((tid & 31) == 0) ws[tid >> 5] = s;
    __syncthreads();
    float tot = ws[0] + ws[1] + ws[2] + ws[3];
    float r = rsqrtf(tot * (1.0f / HID) + EPSV);
    float e[4] = {v.x * r, v.y * r, v.z * r, v.w * r};
    union { uint2 u; __half h[4]; } ph, pl;
#pragma unroll
    for (int j = 0; j < 4; j++) {
        __half hh = __float2half_rn(e[j]);
        ph.h[j] = hh;
        pl.h[j] = __float2half_rn(e[j] - __half2float(hh));
    }
    size_t off = ((size_t)row * HID) / 4 + tid;
    ((uint2*)ahi)[off] = ph.u;
    ((uint2*)alo)[off] = pl.u;
}

// ---------------------------------------------------------------------------
// HMMA split-fp16 GEMM layer.  C[m,n] = sum_k a[m,k] * w_eff[n,k]
// 3 terms: hi*hi + hi*lo + lo*hi, fp32 accum.
// Tile BM=128 x BN=64, BK=32, 256 threads (4x2 warps, 32x32 per warp),
// 3-stage cp.async ring, ONE __syncthreads per stage, 2 CTAs/SM.
// SMEM rows: 32 half = 64 B data, stride 80 B (conflict-free ldmatrix).
// ---------------------------------------------------------------------------
#define RSTRIDE 80
#define A_TILE_BYTES (128 * RSTRIDE)     /* 10240 */
#define B_TILE_BYTES (64 * RSTRIDE)      /* 5120 */
#define STAGE_BYTES (2 * A_TILE_BYTES + 2 * B_TILE_BYTES) /* 30720 */
#define NSTAGE 3
#define SMEM_TOTAL (NSTAGE * STAGE_BYTES) /* 92160 */
#define OFF_AH 0
#define OFF_AL A_TILE_BYTES
#define OFF_BH (2 * A_TILE_BYTES)
#define OFF_BL (2 * A_TILE_BYTES + B_TILE_BYTES)

// A tiles: 128 rows x 4 sixteen-byte units -> 512 cp.async, 2 per thread
__device__ __forceinline__ void load_tileA(uint32_t sbase,
                                           const __half* __restrict__ g,
                                           int rowbase, int kbase, int tid) {
#pragma unroll
    for (int h = 0; h < 2; h++) {
        int u = tid + h * 256;          // 0..511
        int row = u >> 2;
        int un = u & 3;
        uint32_t sa = sbase + row * RSTRIDE + un * 16;
        const void* ga = g + (size_t)(rowbase + row) * HID + kbase + un * 8;
        CP_ASYNC16(sa, ga);
    }
}
// B tiles: 64 rows x 4 units -> 256 cp.async, 1 per thread
__device__ __forceinline__ void load_tileB(uint32_t sbase,
                                           const __half* __restrict__ g,
                                           int rowbase, int kbase, int tid) {
    int row = tid >> 2;
    int un = tid & 3;
    uint32_t sa = sbase + row * RSTRIDE + un * 16;
    const void* ga = g + (size_t)(rowbase + row) * HID + kbase + un * 8;
    CP_ASYNC16(sa, ga);
}

template <bool LAST>
__global__ __launch_bounds__(256, 2) void gemm_layer(
    const __half* __restrict__ Ahi, const __half* __restrict__ Alo,
    const __half* __restrict__ Whi, const __half* __restrict__ Wlo,
    const float* __restrict__ bias, __half* __restrict__ Ohi,
    __half* __restrict__ Olo, float* __restrict__ OutF) {
    extern __shared__ char smem[];
    const uint32_t sb = smem_u32(smem);
    const int tid = threadIdx.x;
    const int wid = tid >> 5;
    const int lid = tid & 31;
    const int wm = wid >> 1;            // 0..3 -> 32 rows each
    const int wn = wid & 1;             // 0..1 -> 32 cols each
    const int bm = blockIdx.y * 128;
    const int bn = blockIdx.x * 64;

    // ldmatrix lane decomposition
    const int lt = lid >> 3;            // tile index 0..3
    const int li = lid & 7;             // row within 8x8 tile

    // Hoisted LDSM offsets (within a stage):
    //  A frag mf at kk: OFF_AH + (am_row+mf*16)*RSTRIDE + (lt>>1)*16 + kk*32
    //  B frag pair p at kk: OFF_BH + (bn_row0+p*16)*RSTRIDE + (lt&1)*16 + kk*32
    const int am_row = wm * 32 + (lt & 1) * 8 + li;
    const int bn_row0 = wn * 32 + (lt >> 1) * 8 + li;
    uint32_t aoff[2], boff[2];
#pragma unroll
    for (int mf = 0; mf < 2; mf++)
        aoff[mf] = OFF_AH + (am_row + mf * 16) * RSTRIDE + (lt >> 1) * 16;
#pragma unroll
    for (int p = 0; p < 2; p++)
        boff[p] = OFF_BH + (bn_row0 + p * 16) * RSTRIDE + (lt & 1) * 16;

    float acc[2][4][4];
#pragma unroll
    for (int a = 0; a < 2; a++)
#pragma unroll
        for (int b = 0; b < 4; b++)
#pragma unroll
            for (int c = 0; c < 4; c++) acc[a][b][c] = 0.0f;

    // prologue: stages 0,1 into buffers 0,1
#pragma unroll
    for (int s = 0; s < 2; s++) {
        uint32_t sp = sb + s * STAGE_BYTES;
        load_tileA(sp + OFF_AH, Ahi, bm, s * 32, tid);
        load_tileA(sp + OFF_AL, Alo, bm, s * 32, tid);
        load_tileB(sp + OFF_BH, Whi, bn, s * 32, tid);
        load_tileB(sp + OFF_BL, Wlo, bn, s * 32, tid);
        CP_COMMIT();
    }

    uint32_t sc = sb;                        // compute buffer (stage s)
    uint32_t sp = sb + 2 * STAGE_BYTES;      // prefetch buffer (stage s+2)

    for (int s = 0; s < 16; s++) {
        // One barrier per stage: everyone finished compute(s-1) before
        // anyone overwrites buffer (s+2)%3 == (s-1)%3.
        __syncthreads();
        if (s + 2 < 16) {
            int kb = (s + 2) * 32;
            load_tileA(sp + OFF_AH, Ahi, bm, kb, tid);
            load_tileA(sp + OFF_AL, Alo, bm, kb, tid);
            load_tileB(sp + OFF_BH, Whi, bn, kb, tid);
            load_tileB(sp + OFF_BL, Wlo, bn, kb, tid);
            CP_COMMIT();
        }
        if (s < 14) CP_WAIT2();
        else if (s == 14) CP_WAIT1();
        else CP_WAIT0();

#pragma unroll
        for (int kk = 0; kk < 2; kk++) {
            uint32_t ah[2][4], al[2][4];
#pragma unroll
            for (int mf = 0; mf < 2; mf++) {
                uint32_t addr = sc + aoff[mf] + kk * 32;
                ldm_x4(addr, ah[mf]);
                ldm_x4(addr + (OFF_AL - OFF_AH), al[mf]);
            }
            uint32_t bh[4][2], bl[4][2];
#pragma unroll
            for (int p = 0; p < 2; p++) {
                uint32_t addr = sc + boff[p] + kk * 32;
                uint32_t r[4];
                ldm_x4(addr, r);
                bh[2 * p][0] = r[0]; bh[2 * p][1] = r[1];
                bh[2 * p + 1][0] = r[2]; bh[2 * p + 1][1] = r[3];
                ldm_x4(addr + (OFF_BL - OFF_BH), r);
                bl[2 * p][0] = r[0]; bl[2 * p][1] = r[1];
                bl[2 * p + 1][0] = r[2]; bl[2 * p + 1][1] = r[3];
            }
            // term-outer ordering: 8 independent accumulators between
            // same-acc reuses
#pragma unroll
            for (int mf = 0; mf < 2; mf++)
#pragma unroll
                for (int nf = 0; nf < 4; nf++)
                    mma16816(acc[mf][nf], ah[mf], bh[nf]);
#pragma unroll
            for (int mf = 0; mf < 2; mf++)
#pragma unroll
                for (int nf = 0; nf < 4; nf++)
                    mma16816(acc[mf][nf], ah[mf], bl[nf]);
#pragma unroll
            for (int mf = 0; mf < 2; mf++)
#pragma unroll
                for (int nf = 0; nf < 4; nf++)
                    mma16816(acc[mf][nf], al[mf], bh[nf]);
        }
        // rotate ring pointers
        sc += STAGE_BYTES;
        if (sc == sb + NSTAGE * STAGE_BYTES) sc = sb;
        sp += STAGE_BYTES;
        if (sp == sb + NSTAGE * STAGE_BYTES) sp = sb;
    }

    // Epilogue: m16n8 c mapping: reg e -> row=(l/4)+(e>=2?8:0),
    // col=(l%4)*2+(e&1)
    float bj[4][2];
#pragma unroll
    for (int nf = 0; nf < 4; nf++) {
        int col = bn + wn * 32 + nf * 8 + (lid & 3) * 2;
        bj[nf][0] = bias[col] * BSCALE;
        bj[nf][1] = bias[col + 1] * BSCALE;
    }

#pragma unroll
    for (int mf = 0; mf < 2; mf++) {
#pragma unroll
        for (int half_ : {0, 1}) {
            int row = bm + wm * 32 + mf * 16 + (lid >> 2) + half_ * 8;
#pragma unroll
            for (int nf = 0; nf < 4; nf++) {
                int col = bn + wn * 32 + nf * 8 + (lid & 3) * 2;
                float x0 = acc[mf][nf][half_ * 2 + 0] + bj[nf][0];
                float x1 = acc[mf][nf][half_ * 2 + 1] + bj[nf][1];
                x0 = (x0 > 0.0f ? x0 : SLOPE * x0) * GAIN;
                x1 = (x1 > 0.0f ? x1 : SLOPE * x1) * GAIN;
                if (!LAST) {
                    __half h0 = __float2half_rn(x0);
                    __half h1 = __float2half_rn(x1);
                    __half l0 = __float2half_rn(x0 - __half2float(h0));
                    __half l1 = __float2half_rn(x1 - __half2float(h1));
                    size_t off = (size_t)row * HID + col;
                    *(__half2*)(Ohi + off) = __halves2half2(h0, h1);
                    *(__half2*)(Olo + off) = __halves2half2(l0, l1);
                } else {
                    float2 p = make_float2(x0, x1);
#pragma unroll
                    for (int r = 0; r < NOUT; r++) {
                        size_t off = ((size_t)row * NOUT + r) * HID + col;
                        *(float2*)(OutF + off) = p;
                    }
                }
            }
        }
    }
}

// ---------------------------------------------------------------------------
extern "C" void kernel_launch(void* const* d_in, const int* in_sizes, int n_in,
                              void* d_out, int out_size) {
    const float* z = (const float*)d_in[0];
    const float* weight = (const float*)d_in[1];
    const float* bias = (const float*)d_in[2];
    float* out = (float*)d_out;

    __half *ahi, *alo, *whi, *wlo;
    cudaGetSymbolAddress((void**)&ahi, g_Ahi);
    cudaGetSymbolAddress((void**)&alo, g_Alo);
    cudaGetSymbolAddress((void**)&whi, g_Whi);
    cudaGetSymbolAddress((void**)&wlo, g_Wlo);

    cudaFuncSetAttribute(gemm_layer<false>,
                         cudaFuncAttributeMaxDynamicSharedMemorySize, SMEM_TOTAL);
    cudaFuncSetAttribute(gemm_layer<true>,
                         cudaFuncAttributeMaxDynamicSharedMemorySize, SMEM_TOTAL);

    wconv_kernel<<<2048, 256>>>(weight, whi, wlo);
    pixelnorm_split_kernel<<<BATCH, 128>>>(z, ahi, alo);

    const size_t ABUF = (size_t)BATCH * HID;
    dim3 grid(HID / 64, BATCH / 128);   // (8, 128) = 1024 CTAs
    for (int l = 0; l < NLAYERS; l++) {
        const __half* Ah = ahi + (l & 1) * ABUF;
        const __half* Al = alo + (l & 1) * ABUF;
        __half* Oh = ahi + ((l + 1) & 1) * ABUF;
        __half* Ol = alo + ((l + 1) & 1) * ABUF;
        const __half* Wh = whi + (size_t)l * HID * HID;
        const __half* Wl = wlo + (size_t)l * HID * HID;
        const float* bl = bias + (size_t)l * HID;
        if (l == NLAYERS - 1)
            gemm_layer<true><<<grid, 256, SMEM_TOTAL>>>(Ah, Al, Wh, Wl, bl,
                                                        nullptr, nullptr, out);
        else
            gemm_layer<false><<<grid, 256, SMEM_TOTAL>>>(Ah, Al, Wh, Wl, bl,
                                                         Oh, Ol, nullptr);
    }
}